// round 7
// baseline (speedup 1.0000x reference)
#include <cuda_runtime.h>

#define N 8192
#define THREADS 256
#define F4_PER_ROW (N / 4)            // 2048 float4 per row
#define ITERS (F4_PER_ROW / THREADS)  // 8 float4 per thread
#define LOG2E 1.44269504088896340736f
#define LN2   0.69314718055994530942f

// softplus in log2 units: log2(1 + 2^x) = max(x,0) + log2(1 + 2^(-|x|))
// log2(1+e) for e in (0,1] replaced by degree-4 Chebyshev-node polynomial
// e*(q0 + e*(q1 + e*(q2 + e*(q3 + e*q4)))), max abs err ~4e-5 (vs 1e-3 budget).
// Saves the MUFU.LG2 (rt=8/SMSP); costs 3 extra fma-pipe ops (rt=2, 31% busy).
__device__ __forceinline__ float softplus2(float x) {
    float e = exp2f(0.0f - fabsf(x));         // single MUFU.EX2
    float t = fmaf(e, 0.059044f, -0.226003f);
    t = fmaf(e, t, 0.441369f);
    t = fmaf(e, t, -0.716995f);
    t = fmaf(e, t, 1.442639f);
    return fmaf(e, t, fmaxf(x, 0.0f));
}

__global__ void __launch_bounds__(THREADS, 8)
bt_row_kernel(const float* __restrict__ win,
              const float* __restrict__ betas,
              float* __restrict__ out) {
    const int row = blockIdx.x;
    const float bi   = __ldg(betas + row);
    const float nbiL = -bi * LOG2E;           // block-uniform

    const float4* wrow = reinterpret_cast<const float4*>(win) + (size_t)row * F4_PER_ROW;
    const float4* b4   = reinterpret_cast<const float4*>(betas);

    float acc0 = 0.0f, acc1 = 0.0f;

    #pragma unroll
    for (int k = 0; k < ITERS; k++) {
        const int p = k * THREADS + threadIdx.x;
        float4 w  = __ldcs(wrow + p);         // streaming, zero reuse
        float4 bj = __ldg(b4 + p);            // L1/L2-resident

        float x0 = fmaf(bj.x, LOG2E, nbiL);
        float x1 = fmaf(bj.y, LOG2E, nbiL);
        float x2 = fmaf(bj.z, LOG2E, nbiL);
        float x3 = fmaf(bj.w, LOG2E, nbiL);

        acc0 = fmaf(w.x, softplus2(x0), acc0);
        acc1 = fmaf(w.y, softplus2(x1), acc1);
        acc0 = fmaf(w.z, softplus2(x2), acc0);
        acc1 = fmaf(w.w, softplus2(x3), acc1);
    }

    float acc = acc0 + acc1;

    // Remove the diagonal term (j == row), recomputed with identical FP ops so
    // the cancellation is exact.
    if (threadIdx.x == 0) {
        float wd = __ldg(win + (size_t)row * N + row);
        float xd = fmaf(bi, LOG2E, nbiL);
        acc -= wd * softplus2(xd);
    }

    // warp reduction
    #pragma unroll
    for (int off = 16; off > 0; off >>= 1)
        acc += __shfl_xor_sync(0xFFFFFFFFu, acc, off);

    __shared__ float warp_sums[THREADS / 32];
    const int lane = threadIdx.x & 31;
    const int wid  = threadIdx.x >> 5;
    if (lane == 0) warp_sums[wid] = acc;
    __syncthreads();

    if (wid == 0) {
        float v = (lane < THREADS / 32) ? warp_sums[lane] : 0.0f;
        #pragma unroll
        for (int off = 4; off > 0; off >>= 1)
            v += __shfl_xor_sync(0xFFFFFFFFu, v, off);
        if (lane == 0)
            atomicAdd(out, v * LN2);          // fire-and-forget RED, no fence
    }
}

extern "C" void kernel_launch(void* const* d_in, const int* in_sizes, int n_in,
                              void* d_out, int out_size) {
    const float* win   = (const float*)d_in[0];
    const float* betas = (const float*)d_in[1];
    float* out = (float*)d_out;

    cudaMemsetAsync(out, 0, sizeof(float));   // graph memset node
    bt_row_kernel<<<N, THREADS>>>(win, betas, out);
}